// round 2
// baseline (speedup 1.0000x reference)
#include <cuda_runtime.h>
#include <cuda_bf16.h>
#include <cstdint>

#define N_TOTAL 8388608   // 2^23
#define LOGN 23

// one scratch buffer (64MB). d_out is used as the other ping-pong buffer.
__device__ float2 g_scratch[N_TOTAL];

__host__ __device__ __forceinline__ constexpr int brev_k(int x, int K) {
    int r = 0;
    for (int b = 0; b < K; b++) r |= ((x >> b) & 1) << (K - 1 - b);
    return r;
}

__device__ __forceinline__ float2 cmul(float2 a, float2 w) {
    // matches reference: (ar*wr - ai*wi, ar*wi + ai*wr)
    return make_float2(a.x * w.x - a.y * w.y, a.x * w.y + a.y * w.x);
}

// ---------------------------------------------------------------------------
// Generic fused group: stages [S0, S0+K). Array viewed as (R=N>>S0, m=2^S0).
// Thread tid handles base=tid: loads X[tid + r*(N>>K)], runs K radix-2 stages
// in registers (in-place, bit-reversed column bookkeeping), writes
// Y[(i<<(S0+K)) + (c<<S0) + j] = a[brev(c)].  Coalesced for m >= 32.
// ---------------------------------------------------------------------------
template <int S0, int K>
__global__ void __launch_bounds__(256) fft_group(const float2* __restrict__ X,
                                                 const float2* __restrict__ W,
                                                 float2* __restrict__ Y) {
    constexpr int L = 1 << K;
    constexpr unsigned STRIDE = (unsigned)N_TOTAL >> K;
    constexpr unsigned m = 1u << S0;

    unsigned tid = blockIdx.x * blockDim.x + threadIdx.x;
    unsigned j = tid & (m - 1u);

    float2 a[L];
#pragma unroll
    for (int r = 0; r < L; r++) a[r] = X[tid + (unsigned)r * STRIDE];

#pragma unroll
    for (int u = 0; u < K; u++) {
        const int half = 1 << (K - 1 - u);
#pragma unroll
        for (int t = 0; t < L / 2; t++) {
            const int q1 = ((t & ~(half - 1)) << 1) | (t & (half - 1));
            const int q2 = q1 + half;
            const int c = brev_k(q1, K) & ((1 << u) - 1);
            // twiddle index = (j + c*m) * 2^(22 - S0 - u)
            unsigned idx = (j << (LOGN - 1 - S0 - u)) +
                           ((unsigned)c << (LOGN - 1 - u));
            float2 w = W[idx];
            float2 p = cmul(a[q2], w);
            float2 tt = a[q1];
            a[q1] = make_float2(tt.x + p.x, tt.y + p.y);
            a[q2] = make_float2(tt.x - p.x, tt.y - p.y);
        }
    }

    unsigned i = tid >> S0;
    unsigned base = (i << (S0 + K)) + j;
#pragma unroll
    for (int c = 0; c < L; c++) {
        const int q = brev_k(c, K);
        Y[base + ((unsigned)c << S0)] = a[q];
    }
}

// ---------------------------------------------------------------------------
// First group (stages 0..4): real input (imag = 0), m = 1.
// Per-thread output is L contiguous complex -> stage through padded smem so
// global writes are lane-contiguous.
// ---------------------------------------------------------------------------
#define K1 5
#define L1 (1 << K1)
#define T1 128

__global__ void __launch_bounds__(T1) fft_first(const float* __restrict__ Xr,
                                                const float2* __restrict__ W,
                                                float2* __restrict__ Y) {
    constexpr unsigned STRIDE = (unsigned)N_TOTAL >> K1;
    unsigned tid = blockIdx.x * T1 + threadIdx.x;

    float2 a[L1];
#pragma unroll
    for (int r = 0; r < L1; r++)
        a[r] = make_float2(Xr[tid + (unsigned)r * STRIDE], 0.0f);

#pragma unroll
    for (int u = 0; u < K1; u++) {
        const int half = 1 << (K1 - 1 - u);
#pragma unroll
        for (int t = 0; t < L1 / 2; t++) {
            const int q1 = ((t & ~(half - 1)) << 1) | (t & (half - 1));
            const int q2 = q1 + half;
            const int c = brev_k(q1, K1) & ((1 << u) - 1);
            unsigned idx = (unsigned)c << (LOGN - 1 - u);  // j = 0, m = 1
            float2 w = W[idx];
            float2 p = cmul(a[q2], w);
            float2 tt = a[q1];
            a[q1] = make_float2(tt.x + p.x, tt.y + p.y);
            a[q2] = make_float2(tt.x - p.x, tt.y - p.y);
        }
    }

    // stage into smem: SoA, row stride T1+1 -> conflict-free on both phases
    __shared__ float sr[L1 * (T1 + 1)];
    __shared__ float si[L1 * (T1 + 1)];
#pragma unroll
    for (int c = 0; c < L1; c++) {
        const int q = brev_k(c, K1);
        sr[c * (T1 + 1) + threadIdx.x] = a[q].x;
        si[c * (T1 + 1) + threadIdx.x] = a[q].y;
    }
    __syncthreads();

    unsigned gbase = blockIdx.x * (T1 * L1);
#pragma unroll
    for (int e = threadIdx.x; e < T1 * L1; e += T1) {
        int c = e & (L1 - 1);
        int t = e >> K1;
        Y[gbase + e] = make_float2(sr[c * (T1 + 1) + t], si[c * (T1 + 1) + t]);
    }
}

// ---------------------------------------------------------------------------
extern "C" void kernel_launch(void* const* d_in, const int* in_sizes, int n_in,
                              void* d_out, int out_size) {
    const float* inp = (const float*)d_in[0];
    const float2* w = (const float2*)d_in[1];
    float2* out = (float2*)d_out;

    float2* scr = nullptr;
    cudaGetSymbolAddress((void**)&scr, g_scratch);

    // stage plan: [0,5) [5,10) [10,15) [15,19) [19,23)
    // buffers:    in -> out -> scr -> out -> scr -> out
    {
        dim3 g(N_TOTAL / (T1 * L1));  // 2048 blocks of 128 threads
        fft_first<<<g, T1>>>(inp, w, out);
    }
    {
        unsigned th = N_TOTAL >> 5;  // 262144
        fft_group<5, 5><<<th / 256, 256>>>(out, w, scr);
        fft_group<10, 5><<<th / 256, 256>>>(scr, w, out);
    }
    {
        unsigned th = N_TOTAL >> 4;  // 524288
        fft_group<15, 4><<<th / 256, 256>>>(out, w, scr);
        fft_group<19, 4><<<th / 256, 256>>>(scr, w, out);
    }
}

// round 3
// speedup vs baseline: 1.6912x; 1.6912x over previous
#include <cuda_runtime.h>
#include <cuda_bf16.h>
#include <cstdint>

#define N_TOTAL 8388608   // 2^23
#define LOGN 23

__device__ float2 g_scratch[N_TOTAL];   // 64MB intermediate (transposed layout)

__host__ __device__ __forceinline__ constexpr int brev_c(int x, int K) {
    int r = 0;
    for (int b = 0; b < K; b++) r |= ((x >> b) & 1) << (K - 1 - b);
    return r;
}

__device__ __forceinline__ float2 cmul(float2 a, float2 w) {
    return make_float2(a.x * w.x - a.y * w.y, a.x * w.y + a.y * w.x);
}

// In-register butterfly network for K stages at global stage offset S0.
// twiddle idx = (jj << (22 - S0 - u)) + (c << (22 - u)); in-place (DIF);
// after the network, register x holds the value for in-tile position x
// (whose final column is bit-reverse of its full position).
template <int S0, int K>
__device__ __forceinline__ void bnet(float2* a, unsigned jj,
                                     const float2* __restrict__ W) {
#pragma unroll
    for (int u = 0; u < K; u++) {
        const int half = 1 << (K - 1 - u);
#pragma unroll
        for (int t = 0; t < (1 << K) / 2; t++) {
            const int q1 = ((t & ~(half - 1)) << 1) | (t & (half - 1));
            const int q2 = q1 + half;
            const int c = brev_c(q1, K) & ((1 << u) - 1);
            unsigned idx = (jj << (22 - S0 - u)) + ((unsigned)c << (22 - u));
            float2 w = W[idx];
            float2 p = cmul(a[q2], w);
            float2 tt = a[q1];
            a[q1] = make_float2(tt.x + p.x, tt.y + p.y);
            a[q2] = make_float2(tt.x - p.x, tt.y - p.y);
        }
    }
}

// ---------------------------------------------------------------------------
// Kernel A: stages [0,11). Block handles 8 consecutive bases (combs of stride
// 4096, 2048 elements each). Rounds 4+4+3 with smem between. j==0 globally so
// all twiddles are warp-uniform. Output transposed: Yt[C*4096 + base].
// ---------------------------------------------------------------------------
#define SMEM_A_FLOATS (2048 * 8 + 256 * 8)   // 18432 per component
#define SMEM_A_BYTES  (SMEM_A_FLOATS * 2 * 4)

__device__ __forceinline__ unsigned physA(unsigned q, unsigned g) {
    return q * 8u + (q >> 3) * 8u + g;
}

__global__ void __launch_bounds__(512, 1)
fft_kA(const float* __restrict__ Xr, const float2* __restrict__ W,
       float2* __restrict__ Yt) {
    extern __shared__ float sm[];
    float* sre = sm;
    float* sim = sm + SMEM_A_FLOATS;

    const unsigned t = threadIdx.x;
    const unsigned g = t & 7u;
    const unsigned rest = t >> 3;            // 0..63
    const unsigned tidA0 = blockIdx.x * 8u;

    // ---- round 1: stages 0..3, register bits q[10:7], load direct from gmem
    for (int it = 0; it < 2; it++) {
        unsigned base = rest + 64u * it;     // q[6:0]
        float2 a[16];
#pragma unroll
        for (int x = 0; x < 16; x++) {
            unsigned q = (unsigned)x * 128u + base;
            a[x] = make_float2(Xr[tidA0 + g + q * 4096u], 0.0f);
        }
        bnet<0, 4>(a, 0u, W);
#pragma unroll
        for (int x = 0; x < 16; x++) {
            unsigned q = (unsigned)x * 128u + base;
            unsigned ph = physA(q, g);
            sre[ph] = a[x].x;
            sim[ph] = a[x].y;
        }
    }
    __syncthreads();

    // ---- round 2: stages 4..7, register bits q[6:3]
    for (int it = 0; it < 2; it++) {
        unsigned idx2 = rest + 64u * it;     // 0..127
        unsigned lo = idx2 & 7u;             // q[2:0]
        unsigned H  = idx2 >> 3;             // q[10:7], 0..15
        float2 a[16];
#pragma unroll
        for (int x = 0; x < 16; x++) {
            unsigned q = H * 128u + (unsigned)x * 8u + lo;
            unsigned ph = physA(q, g);
            a[x] = make_float2(sre[ph], sim[ph]);
        }
        bnet<4, 4>(a, __brev(H) >> 28, W);
#pragma unroll
        for (int x = 0; x < 16; x++) {
            unsigned q = H * 128u + (unsigned)x * 8u + lo;
            unsigned ph = physA(q, g);
            sre[ph] = a[x].x;
            sim[ph] = a[x].y;
        }
    }
    __syncthreads();

    // ---- round 3: stages 8..10, register bits q[2:0]; write gmem transposed
    for (int it = 0; it < 4; it++) {
        unsigned B = rest + 64u * it;        // q[10:3], 0..255
        unsigned Brev = __brev(B) >> 24;
        float2 a[8];
#pragma unroll
        for (int x = 0; x < 8; x++) {
            unsigned q = B * 8u + (unsigned)x;
            unsigned ph = physA(q, g);
            a[x] = make_float2(sre[ph], sim[ph]);
        }
        bnet<8, 3>(a, Brev, W);
#pragma unroll
        for (int x = 0; x < 8; x++) {
            unsigned C = ((unsigned)brev_c(x, 3) << 8) | Brev;  // brev_11(q)
            Yt[C * 4096u + tidA0 + g] = a[x];
        }
    }
}

// ---------------------------------------------------------------------------
// Kernel B: stages [11,23). Block handles 4 consecutive j's; each j's data is
// a contiguous 4096-complex chunk of Yt. Rounds 4+4+4. Output:
// out[(c<<11) + j], c = brev_12(q).
// ---------------------------------------------------------------------------
#define SMEM_B_FLOATS (4096 * 4 + 256 * 4)   // 17408 per component
#define SMEM_B_BYTES  (SMEM_B_FLOATS * 2 * 4)

__device__ __forceinline__ unsigned physB(unsigned q, unsigned jg) {
    return q * 4u + (q >> 4) * 4u + jg;
}

__global__ void __launch_bounds__(512, 1)
fft_kB(const float2* __restrict__ In, const float2* __restrict__ W,
       float2* __restrict__ Out) {
    extern __shared__ float sm[];
    float* sre = sm;
    float* sim = sm + SMEM_B_FLOATS;

    const unsigned t = threadIdx.x;
    const unsigned jg = t & 3u;
    const unsigned rest = t >> 2;            // 0..127
    const unsigned j0 = blockIdx.x * 4u;
    const unsigned jB = j0 + jg;

    // ---- round 1: stages 11..14, register bits q[11:8], load direct gmem
    for (int it = 0; it < 2; it++) {
        unsigned base = rest + 128u * it;    // q[7:0]
        float2 a[16];
#pragma unroll
        for (int x = 0; x < 16; x++) {
            unsigned q = (unsigned)x * 256u + base;
            a[x] = In[jB * 4096u + q];
        }
        bnet<11, 4>(a, jB, W);
#pragma unroll
        for (int x = 0; x < 16; x++) {
            unsigned q = (unsigned)x * 256u + base;
            unsigned ph = physB(q, jg);
            sre[ph] = a[x].x;
            sim[ph] = a[x].y;
        }
    }
    __syncthreads();

    // ---- round 2: stages 15..18, register bits q[7:4]
    for (int it = 0; it < 2; it++) {
        unsigned idx2 = rest + 128u * it;    // 0..255
        unsigned lo = idx2 & 15u;            // q[3:0]
        unsigned H  = idx2 >> 4;             // q[11:8], 0..15
        unsigned jj = jB + ((__brev(H) >> 28) << 11);
        float2 a[16];
#pragma unroll
        for (int x = 0; x < 16; x++) {
            unsigned q = H * 256u + (unsigned)x * 16u + lo;
            unsigned ph = physB(q, jg);
            a[x] = make_float2(sre[ph], sim[ph]);
        }
        bnet<15, 4>(a, jj, W);
#pragma unroll
        for (int x = 0; x < 16; x++) {
            unsigned q = H * 256u + (unsigned)x * 16u + lo;
            unsigned ph = physB(q, jg);
            sre[ph] = a[x].x;
            sim[ph] = a[x].y;
        }
    }
    __syncthreads();

    // ---- round 3: stages 19..22, register bits q[3:0]; write gmem
    for (int it = 0; it < 2; it++) {
        unsigned B = rest + 128u * it;       // q[11:4], 0..255
        unsigned Brev = __brev(B) >> 24;
        unsigned jj = jB + (Brev << 11);
        float2 a[16];
#pragma unroll
        for (int x = 0; x < 16; x++) {
            unsigned q = B * 16u + (unsigned)x;
            unsigned ph = physB(q, jg);
            a[x] = make_float2(sre[ph], sim[ph]);
        }
        bnet<19, 4>(a, jj, W);
#pragma unroll
        for (int x = 0; x < 16; x++) {
            unsigned C = ((unsigned)brev_c(x, 4) << 8) | Brev;  // brev_12(q)
            Out[(C << 11) + jB] = a[x];
        }
    }
}

// ---------------------------------------------------------------------------
extern "C" void kernel_launch(void* const* d_in, const int* in_sizes, int n_in,
                              void* d_out, int out_size) {
    const float* inp = (const float*)d_in[0];
    const float2* w = (const float2*)d_in[1];
    float2* out = (float2*)d_out;

    float2* scr = nullptr;
    cudaGetSymbolAddress((void**)&scr, g_scratch);

    cudaFuncSetAttribute(fft_kA, cudaFuncAttributeMaxDynamicSharedMemorySize,
                         SMEM_A_BYTES);
    cudaFuncSetAttribute(fft_kB, cudaFuncAttributeMaxDynamicSharedMemorySize,
                         SMEM_B_BYTES);

    fft_kA<<<512, 512, SMEM_A_BYTES>>>(inp, w, scr);
    fft_kB<<<512, 512, SMEM_B_BYTES>>>(scr, w, out);
}

// round 4
// speedup vs baseline: 1.7045x; 1.0078x over previous
#include <cuda_runtime.h>
#include <cuda_bf16.h>
#include <cstdint>

#define N_TOTAL 8388608   // 2^23

__device__ float2 g_scratch[N_TOTAL];   // transposed intermediate

__host__ __device__ __forceinline__ constexpr int brev_c(int x, int K) {
    int r = 0;
    for (int b = 0; b < K; b++) r |= ((x >> b) & 1) << (K - 1 - b);
    return r;
}

__device__ __forceinline__ float2 cmul(float2 a, float2 w) {
    return make_float2(a.x * w.x - a.y * w.y, a.x * w.y + a.y * w.x);
}

// In-register DIF butterfly network: K stages at global stage offset S0.
// twiddle idx = (jj << (22-S0-u)) + (c << (22-u)); in-place, bit-reversed c.
template <int S0, int K>
__device__ __forceinline__ void bnet(float2* a, unsigned jj,
                                     const float2* __restrict__ W) {
#pragma unroll
    for (int u = 0; u < K; u++) {
        const int half = 1 << (K - 1 - u);
#pragma unroll
        for (int t = 0; t < (1 << K) / 2; t++) {
            const int q1 = ((t & ~(half - 1)) << 1) | (t & (half - 1));
            const int q2 = q1 + half;
            const int c = brev_c(q1, K) & ((1 << u) - 1);
            unsigned idx = (jj << (22 - S0 - u)) + ((unsigned)c << (22 - u));
            float2 w = W[idx];
            float2 p = cmul(a[q2], w);
            float2 tt = a[q1];
            a[q1] = make_float2(tt.x + p.x, tt.y + p.y);
            a[q2] = make_float2(tt.x - p.x, tt.y - p.y);
        }
    }
}

// ============================================================================
// Kernel A: stages [0,11). Tile = 8 bases (g) x 2048 q. Rounds 3+3+3+2.
// smem: re/im split, XOR swizzle, 128KB total. 1024 threads.
// Output transposed: Yt[C*4096 + base], C = brev11(q).
// ============================================================================
#define SMEM_HALF 16384
#define SMEM_BYTES (SMEM_HALF * 2 * 4)

__device__ __forceinline__ unsigned phA(unsigned q, unsigned g) {
    unsigned l = (q << 3) | g;
    return l ^ (((l >> 5) & 3u) << 3);
}

__global__ void __launch_bounds__(1024, 1)
fft_kA(const float* __restrict__ Xr, const float2* __restrict__ W,
       float2* __restrict__ Yt) {
    extern __shared__ float sm[];
    float* sre = sm;
    float* sim = sm + SMEM_HALF;

    const unsigned t = threadIdx.x;
    const unsigned g = t & 7u;
    const unsigned rest = t >> 3;              // 0..127
    const unsigned base = blockIdx.x * 8u + g;

    // round 1: bits [10:8], S0=0, jj=0 (load from gmem)
#pragma unroll
    for (int pass = 0; pass < 2; pass++) {
        unsigned low8 = rest + 128u * pass;
        float2 a[8];
#pragma unroll
        for (int x = 0; x < 8; x++)
            a[x] = make_float2(Xr[base + ((((unsigned)x << 8) | low8) << 12)], 0.0f);
        bnet<0, 3>(a, 0u, W);
#pragma unroll
        for (int x = 0; x < 8; x++) {
            unsigned q = ((unsigned)x << 8) | low8;
            unsigned ph = phA(q, g);
            sre[ph] = a[x].x;
            sim[ph] = a[x].y;
        }
    }
    __syncthreads();

    // round 2: bits [7:5], S0=3, jj = brev3(q[10:8])
#pragma unroll
    for (int pass = 0; pass < 2; pass++) {
        unsigned low5 = rest & 31u;
        unsigned H = (rest >> 5) | ((unsigned)pass << 2);   // q[10:8]
        unsigned jj = __brev(H) >> 29;
        float2 a[8];
#pragma unroll
        for (int x = 0; x < 8; x++) {
            unsigned q = (H << 8) | ((unsigned)x << 5) | low5;
            unsigned ph = phA(q, g);
            a[x] = make_float2(sre[ph], sim[ph]);
        }
        bnet<3, 3>(a, jj, W);
#pragma unroll
        for (int x = 0; x < 8; x++) {
            unsigned q = (H << 8) | ((unsigned)x << 5) | low5;
            unsigned ph = phA(q, g);
            sre[ph] = a[x].x;
            sim[ph] = a[x].y;
        }
    }
    __syncthreads();

    // round 3: bits [4:2], S0=6, jj = brev6(q[10:5])
#pragma unroll
    for (int pass = 0; pass < 2; pass++) {
        unsigned low2 = rest & 3u;
        unsigned T = (rest >> 2) | ((unsigned)pass << 5);   // q[10:5], 0..63
        unsigned jj = __brev(T) >> 26;
        float2 a[8];
#pragma unroll
        for (int x = 0; x < 8; x++) {
            unsigned q = (T << 5) | ((unsigned)x << 2) | low2;
            unsigned ph = phA(q, g);
            a[x] = make_float2(sre[ph], sim[ph]);
        }
        bnet<6, 3>(a, jj, W);
#pragma unroll
        for (int x = 0; x < 8; x++) {
            unsigned q = (T << 5) | ((unsigned)x << 2) | low2;
            unsigned ph = phA(q, g);
            sre[ph] = a[x].x;
            sim[ph] = a[x].y;
        }
    }
    __syncthreads();

    // round 4: bits [1:0], S0=9, K=2, jj = brev9(q[10:2]); write gmem
#pragma unroll
    for (int pass = 0; pass < 4; pass++) {
        unsigned B = rest + 128u * pass;                    // q[10:2], 0..511
        unsigned jj = __brev(B) >> 23;
        float2 a[4];
#pragma unroll
        for (int x = 0; x < 4; x++) {
            unsigned q = (B << 2) | (unsigned)x;
            unsigned ph = phA(q, g);
            a[x] = make_float2(sre[ph], sim[ph]);
        }
        bnet<9, 2>(a, jj, W);
#pragma unroll
        for (int x = 0; x < 4; x++) {
            unsigned C = ((unsigned)brev_c(x, 2) << 9) | jj;  // brev11(q)
            Yt[C * 4096u + base] = a[x];
        }
    }
}

// ============================================================================
// Kernel B: stages [11,23). Tile = 4 j (jg) x 4096 q. Rounds 3+3+3+3.
// Output: Out[(brev12(q) << 11) + j].
// ============================================================================
__device__ __forceinline__ unsigned phB(unsigned q, unsigned jg) {
    unsigned l = (q << 2) | jg;
    return l ^ (((l >> 5) & 7u) << 2);
}

__global__ void __launch_bounds__(1024, 1)
fft_kB(const float2* __restrict__ In, const float2* __restrict__ W,
       float2* __restrict__ Out) {
    extern __shared__ float sm[];
    float* sre = sm;
    float* sim = sm + SMEM_HALF;

    const unsigned t = threadIdx.x;
    const unsigned jg = t & 3u;
    const unsigned rest = t >> 2;              // 0..255
    const unsigned jB = blockIdx.x * 4u + jg;

    // round 1: bits [11:9], S0=11, jj = jB (load from gmem, contiguous)
#pragma unroll
    for (int pass = 0; pass < 2; pass++) {
        unsigned low9 = rest + 256u * pass;
        float2 a[8];
#pragma unroll
        for (int x = 0; x < 8; x++)
            a[x] = In[jB * 4096u + (((unsigned)x << 9) | low9)];
        bnet<11, 3>(a, jB, W);
#pragma unroll
        for (int x = 0; x < 8; x++) {
            unsigned q = ((unsigned)x << 9) | low9;
            unsigned ph = phB(q, jg);
            sre[ph] = a[x].x;
            sim[ph] = a[x].y;
        }
    }
    __syncthreads();

    // round 2: bits [8:6], S0=14, jj = jB + brev3(q[11:9])<<11
#pragma unroll
    for (int pass = 0; pass < 2; pass++) {
        unsigned low6 = rest & 63u;
        unsigned H = (rest >> 6) | ((unsigned)pass << 2);   // q[11:9]
        unsigned jj = jB + ((__brev(H) >> 29) << 11);
        float2 a[8];
#pragma unroll
        for (int x = 0; x < 8; x++) {
            unsigned q = (H << 9) | ((unsigned)x << 6) | low6;
            unsigned ph = phB(q, jg);
            a[x] = make_float2(sre[ph], sim[ph]);
        }
        bnet<14, 3>(a, jj, W);
#pragma unroll
        for (int x = 0; x < 8; x++) {
            unsigned q = (H << 9) | ((unsigned)x << 6) | low6;
            unsigned ph = phB(q, jg);
            sre[ph] = a[x].x;
            sim[ph] = a[x].y;
        }
    }
    __syncthreads();

    // round 3: bits [5:3], S0=17, jj = jB + brev6(q[11:6])<<11
#pragma unroll
    for (int pass = 0; pass < 2; pass++) {
        unsigned low3 = rest & 7u;
        unsigned T = (rest >> 3) | ((unsigned)pass << 5);   // q[11:6], 0..63
        unsigned jj = jB + ((__brev(T) >> 26) << 11);
        float2 a[8];
#pragma unroll
        for (int x = 0; x < 8; x++) {
            unsigned q = (T << 6) | ((unsigned)x << 3) | low3;
            unsigned ph = phB(q, jg);
            a[x] = make_float2(sre[ph], sim[ph]);
        }
        bnet<17, 3>(a, jj, W);
#pragma unroll
        for (int x = 0; x < 8; x++) {
            unsigned q = (T << 6) | ((unsigned)x << 3) | low3;
            unsigned ph = phB(q, jg);
            sre[ph] = a[x].x;
            sim[ph] = a[x].y;
        }
    }
    __syncthreads();

    // round 4: bits [2:0], S0=20, jj = jB + brev9(q[11:3])<<11; write gmem
#pragma unroll
    for (int pass = 0; pass < 2; pass++) {
        unsigned B = rest + 256u * pass;                    // q[11:3], 0..511
        unsigned Brev = __brev(B) >> 23;
        unsigned jj = jB + (Brev << 11);
        float2 a[8];
#pragma unroll
        for (int x = 0; x < 8; x++) {
            unsigned q = (B << 3) | (unsigned)x;
            unsigned ph = phB(q, jg);
            a[x] = make_float2(sre[ph], sim[ph]);
        }
        bnet<20, 3>(a, jj, W);
#pragma unroll
        for (int x = 0; x < 8; x++) {
            unsigned C = ((unsigned)brev_c(x, 3) << 9) | Brev;  // brev12(q)
            Out[(C << 11) + jB] = a[x];
        }
    }
}

// ---------------------------------------------------------------------------
extern "C" void kernel_launch(void* const* d_in, const int* in_sizes, int n_in,
                              void* d_out, int out_size) {
    const float* inp = (const float*)d_in[0];
    const float2* w = (const float2*)d_in[1];
    float2* out = (float2*)d_out;

    float2* scr = nullptr;
    cudaGetSymbolAddress((void**)&scr, g_scratch);

    cudaFuncSetAttribute(fft_kA, cudaFuncAttributeMaxDynamicSharedMemorySize,
                         SMEM_BYTES);
    cudaFuncSetAttribute(fft_kB, cudaFuncAttributeMaxDynamicSharedMemorySize,
                         SMEM_BYTES);

    fft_kA<<<512, 1024, SMEM_BYTES>>>(inp, w, scr);   // stages 0..10
    fft_kB<<<512, 1024, SMEM_BYTES>>>(scr, w, out);   // stages 11..22
}

// round 5
// speedup vs baseline: 1.8407x; 1.0800x over previous
#include <cuda_runtime.h>
#include <cuda_bf16.h>
#include <cstdint>

#define N_TOTAL 8388608   // 2^23

__device__ float2 g_scratch[N_TOTAL];   // transposed intermediate

__host__ __device__ __forceinline__ constexpr int brev_c(int x, int K) {
    int r = 0;
    for (int b = 0; b < K; b++) r |= ((x >> b) & 1) << (K - 1 - b);
    return r;
}

__device__ __forceinline__ float2 cmul(float2 a, float2 w) {
    return make_float2(a.x * w.x - a.y * w.y, a.x * w.y + a.y * w.x);
}

// In-register DIF butterfly network, K stages at global stage offset S0,
// with ALL twiddles prefetched up front (indices are data-independent).
// twiddle idx = (jj << (22-S0-u)) + (c << (22-u)).
template <int S0, int K>
__device__ __forceinline__ void bnet_pf(float2* a, unsigned jj,
                                        const float2* __restrict__ W) {
    float2 tw[(1 << K) - 1];
    // prefetch: issue all loads before any use -> MLP instead of serial chain
#pragma unroll
    for (int u = 0; u < K; u++) {
#pragma unroll
        for (int c = 0; c < (1 << u); c++) {
            unsigned idx = (jj << (22 - S0 - u)) + ((unsigned)c << (22 - u));
            tw[(1 << u) - 1 + c] = __ldg(&W[idx]);
        }
    }
#pragma unroll
    for (int u = 0; u < K; u++) {
        const int half = 1 << (K - 1 - u);
#pragma unroll
        for (int t = 0; t < (1 << K) / 2; t++) {
            const int q1 = ((t & ~(half - 1)) << 1) | (t & (half - 1));
            const int q2 = q1 + half;
            const int c = brev_c(q1, K) & ((1 << u) - 1);
            float2 w = tw[(1 << u) - 1 + c];
            float2 p = cmul(a[q2], w);
            float2 tt = a[q1];
            a[q1] = make_float2(tt.x + p.x, tt.y + p.y);
            a[q2] = make_float2(tt.x - p.x, tt.y - p.y);
        }
    }
}

#define SMEM_HALF 16384
#define SMEM_BYTES (SMEM_HALF * 2 * 4)

// ============================================================================
// Kernel A: stages [0,11). Tile = 8 bases (g) x 2048 q. Rounds 4+4+3,
// two smem round-trips. 512 threads. Output transposed: Yt[brev11(q)*4096+base]
// ============================================================================
__device__ __forceinline__ unsigned phA(unsigned q, unsigned g) {
    unsigned l = (q << 3) | g;
    return l ^ (((l >> 6) & 3u) << 3);
}

__global__ void __launch_bounds__(512, 1)
fft_kA(const float* __restrict__ Xr, const float2* __restrict__ W,
       float2* __restrict__ Yt) {
    extern __shared__ float sm[];
    float* sre = sm;
    float* sim = sm + SMEM_HALF;

    const unsigned t = threadIdx.x;
    const unsigned g = t & 7u;
    const unsigned rest = t >> 3;              // 0..63
    const unsigned base = blockIdx.x * 8u + g;

    // round 1: bits q[10:7], S0=0, jj=0 (gmem load, imag=0)
#pragma unroll
    for (int pass = 0; pass < 2; pass++) {
        unsigned low7 = rest + 64u * pass;     // q[6:0]
        float2 a[16];
#pragma unroll
        for (int x = 0; x < 16; x++)
            a[x] = make_float2(
                __ldg(&Xr[base + ((((unsigned)x << 7) | low7) << 12)]), 0.0f);
        bnet_pf<0, 4>(a, 0u, W);
#pragma unroll
        for (int x = 0; x < 16; x++) {
            unsigned q = ((unsigned)x << 7) | low7;
            unsigned ph = phA(q, g);
            sre[ph] = a[x].x;
            sim[ph] = a[x].y;
        }
    }
    __syncthreads();

    // round 2: bits q[6:3], S0=4, jj = brev4(q[10:7])
#pragma unroll
    for (int pass = 0; pass < 2; pass++) {
        unsigned idx2 = rest + 64u * pass;     // 0..127
        unsigned lo3 = idx2 & 7u;              // q[2:0]
        unsigned H = idx2 >> 3;                // q[10:7]
        unsigned jj = __brev(H) >> 28;
        float2 a[16];
#pragma unroll
        for (int x = 0; x < 16; x++) {
            unsigned q = (H << 7) | ((unsigned)x << 3) | lo3;
            unsigned ph = phA(q, g);
            a[x] = make_float2(sre[ph], sim[ph]);
        }
        bnet_pf<4, 4>(a, jj, W);
#pragma unroll
        for (int x = 0; x < 16; x++) {
            unsigned q = (H << 7) | ((unsigned)x << 3) | lo3;
            unsigned ph = phA(q, g);
            sre[ph] = a[x].x;
            sim[ph] = a[x].y;
        }
    }
    __syncthreads();

    // round 3: bits q[2:0], S0=8, K=3, jj = brev8(q[10:3]); write transposed
#pragma unroll
    for (int pass = 0; pass < 4; pass++) {
        unsigned B = rest + 64u * pass;        // q[10:3], 0..255
        unsigned jj = __brev(B) >> 24;
        float2 a[8];
#pragma unroll
        for (int x = 0; x < 8; x++) {
            unsigned q = (B << 3) | (unsigned)x;
            unsigned ph = phA(q, g);
            a[x] = make_float2(sre[ph], sim[ph]);
        }
        bnet_pf<8, 3>(a, jj, W);
#pragma unroll
        for (int x = 0; x < 8; x++) {
            unsigned C = ((unsigned)brev_c(x, 3) << 8) | jj;  // brev11(q)
            Yt[C * 4096u + base] = a[x];
        }
    }
}

// ============================================================================
// Kernel B: stages [11,23). Tile = 4 j (jg) x 4096 q. Rounds 4+4+4,
// two smem round-trips. 512 threads. Output: Out[(brev12(q) << 11) + j].
// ============================================================================
__device__ __forceinline__ unsigned phB(unsigned q, unsigned jg) {
    unsigned l = (q << 2) | jg;
    return l ^ (((l >> 6) & 7u) << 2);
}

__global__ void __launch_bounds__(512, 1)
fft_kB(const float2* __restrict__ In, const float2* __restrict__ W,
       float2* __restrict__ Out) {
    extern __shared__ float sm[];
    float* sre = sm;
    float* sim = sm + SMEM_HALF;

    const unsigned t = threadIdx.x;
    const unsigned jg = t & 3u;
    const unsigned rest = t >> 2;              // 0..127
    const unsigned jB = blockIdx.x * 4u + jg;

    // round 1: bits q[11:8], S0=11, jj = jB (contiguous gmem load)
#pragma unroll
    for (int pass = 0; pass < 2; pass++) {
        unsigned low8 = rest + 128u * pass;    // q[7:0]
        float2 a[16];
#pragma unroll
        for (int x = 0; x < 16; x++)
            a[x] = __ldg(&In[jB * 4096u + (((unsigned)x << 8) | low8)]);
        bnet_pf<11, 4>(a, jB, W);
#pragma unroll
        for (int x = 0; x < 16; x++) {
            unsigned q = ((unsigned)x << 8) | low8;
            unsigned ph = phB(q, jg);
            sre[ph] = a[x].x;
            sim[ph] = a[x].y;
        }
    }
    __syncthreads();

    // round 2: bits q[7:4], S0=15, jj = jB + brev4(q[11:8])<<11
#pragma unroll
    for (int pass = 0; pass < 2; pass++) {
        unsigned idx2 = rest + 128u * pass;    // 0..255
        unsigned lo4 = idx2 & 15u;             // q[3:0]
        unsigned H = idx2 >> 4;                // q[11:8]
        unsigned jj = jB + ((__brev(H) >> 28) << 11);
        float2 a[16];
#pragma unroll
        for (int x = 0; x < 16; x++) {
            unsigned q = (H << 8) | ((unsigned)x << 4) | lo4;
            unsigned ph = phB(q, jg);
            a[x] = make_float2(sre[ph], sim[ph]);
        }
        bnet_pf<15, 4>(a, jj, W);
#pragma unroll
        for (int x = 0; x < 16; x++) {
            unsigned q = (H << 8) | ((unsigned)x << 4) | lo4;
            unsigned ph = phB(q, jg);
            sre[ph] = a[x].x;
            sim[ph] = a[x].y;
        }
    }
    __syncthreads();

    // round 3: bits q[3:0], S0=19, jj = jB + brev8(q[11:4])<<11; write out
#pragma unroll
    for (int pass = 0; pass < 2; pass++) {
        unsigned B = rest + 128u * pass;       // q[11:4], 0..255
        unsigned Brev = __brev(B) >> 24;
        unsigned jj = jB + (Brev << 11);
        float2 a[16];
#pragma unroll
        for (int x = 0; x < 16; x++) {
            unsigned q = (B << 4) | (unsigned)x;
            unsigned ph = phB(q, jg);
            a[x] = make_float2(sre[ph], sim[ph]);
        }
        bnet_pf<19, 4>(a, jj, W);
#pragma unroll
        for (int x = 0; x < 16; x++) {
            unsigned C = ((unsigned)brev_c(x, 4) << 8) | Brev;  // brev12(q)
            Out[(C << 11) + jB] = a[x];
        }
    }
}

// ---------------------------------------------------------------------------
extern "C" void kernel_launch(void* const* d_in, const int* in_sizes, int n_in,
                              void* d_out, int out_size) {
    const float* inp = (const float*)d_in[0];
    const float2* w = (const float2*)d_in[1];
    float2* out = (float2*)d_out;

    float2* scr = nullptr;
    cudaGetSymbolAddress((void**)&scr, g_scratch);

    cudaFuncSetAttribute(fft_kA, cudaFuncAttributeMaxDynamicSharedMemorySize,
                         SMEM_BYTES);
    cudaFuncSetAttribute(fft_kB, cudaFuncAttributeMaxDynamicSharedMemorySize,
                         SMEM_BYTES);

    fft_kA<<<512, 512, SMEM_BYTES>>>(inp, w, scr);   // stages 0..10
    fft_kB<<<512, 512, SMEM_BYTES>>>(scr, w, out);   // stages 11..22
}

// round 6
// speedup vs baseline: 2.0352x; 1.1057x over previous
#include <cuda_runtime.h>
#include <cuda_bf16.h>
#include <cstdint>

#define N_TOTAL 8388608   // 2^23

__device__ float2 g_scratch[N_TOTAL];   // transposed intermediate

__host__ __device__ __forceinline__ constexpr int brev_c(int x, int K) {
    int r = 0;
    for (int b = 0; b < K; b++) r |= ((x >> b) & 1) << (K - 1 - b);
    return r;
}

__device__ __forceinline__ float2 cmul(float2 a, float2 w) {
    return make_float2(a.x * w.x - a.y * w.y, a.x * w.y + a.y * w.x);
}

// In-register DIF butterfly network, K stages at global stage offset S0,
// all twiddles prefetched up front (indices data-independent).
template <int S0, int K>
__device__ __forceinline__ void bnet_pf(float2* a, unsigned jj,
                                        const float2* __restrict__ W) {
    float2 tw[(1 << K) - 1];
#pragma unroll
    for (int u = 0; u < K; u++) {
#pragma unroll
        for (int c = 0; c < (1 << u); c++) {
            unsigned idx = (jj << (22 - S0 - u)) + ((unsigned)c << (22 - u));
            tw[(1 << u) - 1 + c] = __ldg(&W[idx]);
        }
    }
#pragma unroll
    for (int u = 0; u < K; u++) {
        const int half = 1 << (K - 1 - u);
#pragma unroll
        for (int t = 0; t < (1 << K) / 2; t++) {
            const int q1 = ((t & ~(half - 1)) << 1) | (t & (half - 1));
            const int q2 = q1 + half;
            const int c = brev_c(q1, K) & ((1 << u) - 1);
            float2 w = tw[(1 << u) - 1 + c];
            float2 p = cmul(a[q2], w);
            float2 tt = a[q1];
            a[q1] = make_float2(tt.x + p.x, tt.y + p.y);
            a[q2] = make_float2(tt.x - p.x, tt.y - p.y);
        }
    }
}

#define SMEM_ELEMS 16384
#define SMEM_BYTES (SMEM_ELEMS * 8)

// ============================================================================
// Kernel A: stages [0,11). Tile = 8 bases (g) x 2048 q. Rounds 4+4+3.
// float2 smem, XOR swizzle (verified conflict-free all rounds).
// Output transposed: Yt[brev11(q)*4096 + base].
// ============================================================================
__device__ __forceinline__ unsigned phA(unsigned q, unsigned g) {
    unsigned l = (q << 3) | g;
    return l ^ (((l >> 6) & 1u) << 3);
}

__global__ void __launch_bounds__(512, 1)
fft_kA(const float* __restrict__ Xr, const float2* __restrict__ W,
       float2* __restrict__ Yt) {
    extern __shared__ float2 sm2[];

    const unsigned t = threadIdx.x;
    const unsigned g = t & 7u;
    const unsigned rest = t >> 3;              // 0..63
    const unsigned base = blockIdx.x * 8u + g;

    // round 1: bits q[10:7], S0=0, jj=0 (gmem load, imag=0)
#pragma unroll
    for (int pass = 0; pass < 2; pass++) {
        unsigned low7 = rest + 64u * pass;     // q[6:0]
        float2 a[16];
#pragma unroll
        for (int x = 0; x < 16; x++)
            a[x] = make_float2(
                __ldg(&Xr[base + ((((unsigned)x << 7) | low7) << 12)]), 0.0f);
        bnet_pf<0, 4>(a, 0u, W);
#pragma unroll
        for (int x = 0; x < 16; x++) {
            unsigned q = ((unsigned)x << 7) | low7;
            sm2[phA(q, g)] = a[x];
        }
    }
    __syncthreads();

    // round 2: bits q[6:3], S0=4, jj = brev4(q[10:7])
#pragma unroll
    for (int pass = 0; pass < 2; pass++) {
        unsigned idx2 = rest + 64u * pass;     // 0..127
        unsigned lo3 = idx2 & 7u;              // q[2:0]
        unsigned H = idx2 >> 3;                // q[10:7]
        unsigned jj = __brev(H) >> 28;
        float2 a[16];
#pragma unroll
        for (int x = 0; x < 16; x++) {
            unsigned q = (H << 7) | ((unsigned)x << 3) | lo3;
            a[x] = sm2[phA(q, g)];
        }
        bnet_pf<4, 4>(a, jj, W);
#pragma unroll
        for (int x = 0; x < 16; x++) {
            unsigned q = (H << 7) | ((unsigned)x << 3) | lo3;
            sm2[phA(q, g)] = a[x];
        }
    }
    __syncthreads();

    // round 3: bits q[2:0], S0=8, K=3, jj = brev8(q[10:3]); write transposed
#pragma unroll
    for (int pass = 0; pass < 4; pass++) {
        unsigned B = rest + 64u * pass;        // q[10:3], 0..255
        unsigned jj = __brev(B) >> 24;
        float2 a[8];
#pragma unroll
        for (int x = 0; x < 8; x++) {
            unsigned q = (B << 3) | (unsigned)x;
            a[x] = sm2[phA(q, g)];
        }
        bnet_pf<8, 3>(a, jj, W);
#pragma unroll
        for (int x = 0; x < 8; x++) {
            unsigned C = ((unsigned)brev_c(x, 3) << 8) | jj;  // brev11(q)
            Yt[C * 4096u + base] = a[x];
        }
    }
}

// ============================================================================
// Kernel B: stages [11,23). Tile = 4 j x 4096 q. Rounds 4+4+4.
// Round 1 lane map: 32 consecutive q per warp, single jB -> coalesced data
// loads + warp-uniform twiddles. float2 smem + XOR swizzle.
// Output: Out[(brev12(q) << 11) + j].
// ============================================================================
__device__ __forceinline__ unsigned phB(unsigned q, unsigned js) {
    unsigned l = (q << 2) | js;
    return l ^ ((l >> 4) & 3u) ^ (((l >> 6) & 3u) << 2);
}

__global__ void __launch_bounds__(512, 1)
fft_kB(const float2* __restrict__ In, const float2* __restrict__ W,
       float2* __restrict__ Out) {
    extern __shared__ float2 sm2[];

    const unsigned t = threadIdx.x;
    const unsigned j0 = blockIdx.x * 4u;

    // round 1: bits q[11:8], S0=11. Lane map: jg1 = t>>7 (warp-uniform jB),
    // lowt = t&127 -> 32 consecutive q per warp => coalesced LDG + uniform W.
    {
        const unsigned jg1 = t >> 7;           // 0..3
        const unsigned lowt = t & 127u;
        const unsigned jB1 = j0 + jg1;
#pragma unroll
        for (int pass = 0; pass < 2; pass++) {
            unsigned low8 = lowt + 128u * pass;  // q[7:0]
            float2 a[16];
#pragma unroll
            for (int x = 0; x < 16; x++)
                a[x] = __ldg(&In[jB1 * 4096u + (((unsigned)x << 8) | low8)]);
            bnet_pf<11, 4>(a, jB1, W);
#pragma unroll
            for (int x = 0; x < 16; x++) {
                unsigned q = ((unsigned)x << 8) | low8;
                sm2[phB(q, jg1)] = a[x];
            }
        }
    }
    __syncthreads();

    const unsigned jg = t & 3u;
    const unsigned rest = t >> 2;              // 0..127
    const unsigned jB = j0 + jg;

    // round 2: bits q[7:4], S0=15, jj = jB + brev4(q[11:8])<<11
#pragma unroll
    for (int pass = 0; pass < 2; pass++) {
        unsigned idx2 = rest + 128u * pass;    // 0..255
        unsigned lo4 = idx2 & 15u;             // q[3:0]
        unsigned H = idx2 >> 4;                // q[11:8]
        unsigned jj = jB + ((__brev(H) >> 28) << 11);
        float2 a[16];
#pragma unroll
        for (int x = 0; x < 16; x++) {
            unsigned q = (H << 8) | ((unsigned)x << 4) | lo4;
            a[x] = sm2[phB(q, jg)];
        }
        bnet_pf<15, 4>(a, jj, W);
#pragma unroll
        for (int x = 0; x < 16; x++) {
            unsigned q = (H << 8) | ((unsigned)x << 4) | lo4;
            sm2[phB(q, jg)] = a[x];
        }
    }
    __syncthreads();

    // round 3: bits q[3:0], S0=19, jj = jB + brev8(q[11:4])<<11; write out
#pragma unroll
    for (int pass = 0; pass < 2; pass++) {
        unsigned B = rest + 128u * pass;       // q[11:4], 0..255
        unsigned Brev = __brev(B) >> 24;
        unsigned jj = jB + (Brev << 11);
        float2 a[16];
#pragma unroll
        for (int x = 0; x < 16; x++) {
            unsigned q = (B << 4) | (unsigned)x;
            a[x] = sm2[phB(q, jg)];
        }
        bnet_pf<19, 4>(a, jj, W);
#pragma unroll
        for (int x = 0; x < 16; x++) {
            unsigned C = ((unsigned)brev_c(x, 4) << 8) | Brev;  // brev12(q)
            Out[(C << 11) + jB] = a[x];
        }
    }
}

// ---------------------------------------------------------------------------
extern "C" void kernel_launch(void* const* d_in, const int* in_sizes, int n_in,
                              void* d_out, int out_size) {
    const float* inp = (const float*)d_in[0];
    const float2* w = (const float2*)d_in[1];
    float2* out = (float2*)d_out;

    float2* scr = nullptr;
    cudaGetSymbolAddress((void**)&scr, g_scratch);

    cudaFuncSetAttribute(fft_kA, cudaFuncAttributeMaxDynamicSharedMemorySize,
                         SMEM_BYTES);
    cudaFuncSetAttribute(fft_kB, cudaFuncAttributeMaxDynamicSharedMemorySize,
                         SMEM_BYTES);

    fft_kA<<<512, 512, SMEM_BYTES>>>(inp, w, scr);   // stages 0..10
    fft_kB<<<512, 512, SMEM_BYTES>>>(scr, w, out);   // stages 11..22
}